// round 3
// baseline (speedup 1.0000x reference)
#include <cuda_runtime.h>
#include <math.h>

// LSTM: B=128, T=1024, D=512, H=512.
// Persistent kernel: 128 CTAs = 2 batch tiles (64 rows) x 64 h-col tiles (8 h cols -> 32 gate cols).
// W slice resident in SMEM; h broadcast via L2 + device-wide sense-reversal barrier each step.
// fp32 math via packed fma.rn.f32x2 (2 FMA per fma-pipe slot).

#define NB 128
#define NT 1024
#define ND 512
#define NH 512
#define K_TOT 1024
#define GRID 128
#define THREADS 256
#define ROWS_CTA 64
#define KC 64

__device__ volatile unsigned g_sense;
__device__ unsigned g_count;
__device__ float g_hbuf[2][NB * NH];

__device__ __forceinline__ unsigned long long pack2(float lo, float hi) {
    unsigned long long r;
    asm("mov.b64 %0, {%1,%2};" : "=l"(r) : "f"(lo), "f"(hi));
    return r;
}
__device__ __forceinline__ void unpack2(unsigned long long v, float& lo, float& hi) {
    asm("mov.b64 {%0,%1}, %2;" : "=f"(lo), "=f"(hi) : "l"(v));
}
#define FMA2(acc, a, w) \
    asm("fma.rn.f32x2 %0, %1, %2, %0;" : "+l"(acc) : "l"(a), "l"(w))

__device__ __forceinline__ float sigf(float x) { return 1.0f / (1.0f + expf(-x)); }

__global__ void __launch_bounds__(THREADS, 1) lstm_persistent(
    const float* __restrict__ obs, const float* __restrict__ Wi,
    const float* __restrict__ Wh, const float* __restrict__ bv,
    const float* __restrict__ c0, const float* __restrict__ h0,
    float* __restrict__ out, int out_size)
{
    extern __shared__ float sm[];
    // W2: float2[1024][16]  (32768 floats)  -- packed col pairs of this CTA's 32 gate cols
    // A2: float2[64][66]    (8448 floats)   -- duplicated A values, pitch-padded
    // Y2: float2[64][17]    (2176 floats)   -- gate pre-activations for combine
    float2* W2 = (float2*)sm;
    float2* A2 = (float2*)(sm + 32768);
    float2* Y2 = (float2*)(sm + 32768 + 8448);

    const int tid = threadIdx.x;
    const int tx = tid & 15;
    const int ty = tid >> 4;
    const int bi = blockIdx.x >> 6;       // 0..1 batch tile
    const int hj = blockIdx.x & 63;       // h-col tile
    const int row0 = bi * ROWS_CTA;
    const int hcol0 = hj * 8;

    // ---- one-time: fill W slice (rows 0..511 from Wi, 512..1023 from Wh) ----
    for (int idx = tid; idx < K_TOT * 16; idx += THREADS) {
        int k = idx >> 4, j = idx & 15;
        int cA = 2 * j, cB = 2 * j + 1;
        int gA = ((cA >> 3) << 9) + hcol0 + (cA & 7);
        int gB = ((cB >> 3) << 9) + hcol0 + (cB & 7);
        float vA, vB;
        if (k < ND) { vA = Wi[k * 2048 + gA]; vB = Wi[k * 2048 + gB]; }
        else        { vA = Wh[(k - ND) * 2048 + gA]; vB = Wh[(k - ND) * 2048 + gB]; }
        W2[idx] = make_float2(vA, vB);
    }

    // bias for this thread's two gate columns
    const int c0l = 2 * tx, c1l = 2 * tx + 1;
    const int gb0 = ((c0l >> 3) << 9) + hcol0 + (c0l & 7);
    const int gb1 = ((c1l >> 3) << 9) + hcol0 + (c1l & 7);
    const unsigned long long bias2 = pack2(bv[gb0], bv[gb1]);

    // elementwise ownership: two (row, hcol) pairs per thread; c kept in registers
    const int p0 = tid, p1 = tid + 256;
    const int r_p0 = p0 >> 3, h_p0 = p0 & 7;
    const int r_p1 = p1 >> 3, h_p1 = p1 & 7;
    const int gi0 = (row0 + r_p0) * NH + hcol0 + h_p0;
    const int gi1 = (row0 + r_p1) * NH + hcol0 + h_p1;
    float cs0 = c0[gi0], cs1 = c0[gi1];

    __syncthreads();

    const unsigned long long* a_base =
        (const unsigned long long*)(A2 + (4 * ty) * 66);
    float rg[16];

    for (int t = 0; t < NT; ++t) {
        const float* hsrc = (t == 0) ? h0 : (const float*)g_hbuf[t & 1];
        unsigned long long acc0 = bias2, acc1 = bias2, acc2 = bias2, acc3 = bias2;

        // prologue: load K-chunk 0 (pure obs) into registers
        #pragma unroll
        for (int i = 0; i < 16; ++i) {
            int e = tid + (i << 8);
            int r = e >> 6, k = e & 63;
            rg[i] = obs[((row0 + r) * NT + t) * ND + k];
        }

        for (int ch = 0; ch < 16; ++ch) {
            __syncthreads();
            // store staged chunk to SMEM (duplicated for f32x2 broadcast)
            #pragma unroll
            for (int i = 0; i < 16; ++i) {
                int e = tid + (i << 8);
                int r = e >> 6, k = e & 63;
                A2[r * 66 + k] = make_float2(rg[i], rg[i]);
            }
            __syncthreads();
            // prefetch next chunk (overlaps with compute below)
            if (ch < 15) {
                int kg0 = (ch + 1) * KC;
                #pragma unroll
                for (int i = 0; i < 16; ++i) {
                    int e = tid + (i << 8);
                    int r = e >> 6, k = e & 63;
                    int kg = kg0 + k;
                    if (kg < ND)
                        rg[i] = obs[((row0 + r) * NT + t) * ND + kg];
                    else
                        rg[i] = __ldcg(hsrc + (row0 + r) * NH + (kg - ND));
                }
            }
            // compute: 64 k-iters, 4 rows x 2 packed cols per thread
            const unsigned long long* wp =
                (const unsigned long long*)(W2 + ch * KC * 16) + tx;
            #pragma unroll 8
            for (int kk = 0; kk < KC; ++kk) {
                unsigned long long w  = wp[kk * 16];
                unsigned long long a0 = a_base[kk];
                unsigned long long a1 = a_base[66 + kk];
                unsigned long long a2 = a_base[132 + kk];
                unsigned long long a3 = a_base[198 + kk];
                FMA2(acc0, a0, w);
                FMA2(acc1, a1, w);
                FMA2(acc2, a2, w);
                FMA2(acc3, a3, w);
            }
        }

        // publish gate pre-activations to SMEM for cross-thread combine
        {
            float lo, hi;
            unpack2(acc0, lo, hi); Y2[(4 * ty + 0) * 17 + tx] = make_float2(lo, hi);
            unpack2(acc1, lo, hi); Y2[(4 * ty + 1) * 17 + tx] = make_float2(lo, hi);
            unpack2(acc2, lo, hi); Y2[(4 * ty + 2) * 17 + tx] = make_float2(lo, hi);
            unpack2(acc3, lo, hi); Y2[(4 * ty + 3) * 17 + tx] = make_float2(lo, hi);
        }
        __syncthreads();

        const float* Yf = (const float*)Y2;
        float hn0, hn1;
        {
            float iv = Yf[r_p0 * 34 + h_p0];
            float fv = Yf[r_p0 * 34 + 8 + h_p0];
            float gv = Yf[r_p0 * 34 + 16 + h_p0];
            float ov = Yf[r_p0 * 34 + 24 + h_p0];
            cs0 = sigf(fv) * cs0 + sigf(iv) * tanhf(gv);
            hn0 = sigf(ov) * tanhf(cs0);
        }
        {
            float iv = Yf[r_p1 * 34 + h_p1];
            float fv = Yf[r_p1 * 34 + 8 + h_p1];
            float gv = Yf[r_p1 * 34 + 16 + h_p1];
            float ov = Yf[r_p1 * 34 + 24 + h_p1];
            cs1 = sigf(fv) * cs1 + sigf(iv) * tanhf(gv);
            hn1 = sigf(ov) * tanhf(cs1);
        }

        // h for next step + contexts output
        float* hdst = g_hbuf[(t + 1) & 1];
        hdst[gi0] = hn0;
        hdst[gi1] = hn1;
        out[((row0 + r_p0) * NT + t) * NH + hcol0 + h_p0] = hn0;
        out[((row0 + r_p1) * NT + t) * NH + hcol0 + h_p1] = hn1;
        if (t == NT - 1) {
            int base = NB * NT * NH;  // 67,108,864 (fits in int)
            if (out_size >= base + 2 * NB * NH) {
                out[base + gi0] = cs0;              // cT
                out[base + gi1] = cs1;
                out[base + NB * NH + gi0] = hn0;    // hT
                out[base + NB * NH + gi1] = hn1;
            }
        }

        // device-wide sense-reversal barrier (1024 total -> sense returns to 0)
        __threadfence();
        __syncthreads();
        if (tid == 0) {
            const unsigned target = (unsigned)((t & 1) ^ 1);
            if (atomicAdd(&g_count, 1u) == GRID - 1) {
                g_count = 0;
                __threadfence();
                g_sense = target;
            } else {
                while (g_sense != target) { }
                __threadfence();
            }
        }
        __syncthreads();
    }
}

extern "C" void kernel_launch(void* const* d_in, const int* in_sizes, int n_in,
                              void* d_out, int out_size)
{
    const float* obs = (const float*)d_in[0];
    const float* Wi  = (const float*)d_in[1];
    const float* Wh  = (const float*)d_in[2];
    const float* bv  = (const float*)d_in[3];
    const float* c0  = (const float*)d_in[4];
    const float* h0  = (const float*)d_in[5];

    const int smem_bytes = (32768 + 8448 + 2176) * 4;  // 173,568 B
    cudaFuncSetAttribute(lstm_persistent,
                         cudaFuncAttributeMaxDynamicSharedMemorySize, smem_bytes);
    lstm_persistent<<<GRID, THREADS, smem_bytes>>>(obs, Wi, Wh, bv, c0, h0,
                                                   (float*)d_out, out_size);
}

// round 4
// speedup vs baseline: 1.0691x; 1.0691x over previous
#include <cuda_runtime.h>
#include <math.h>

// LSTM: B=128, T=1024, D=512, H=512.
// Persistent kernel: 128 CTAs = 2 batch tiles (64 rows) x 64 h-col tiles (8 h cols -> 32 gate cols).
// W slice resident in SMEM as float4 (4 packed gate cols); A duplicated-pair float4 covers 2 k per LDS.128.
// Per-thread tile: 2 rows x 2 f32x2 col-pairs -> 4 LDS.128 + 8 FMA2 per 2 k.

#define NB 128
#define NT 1024
#define ND 512
#define NH 512
#define K_TOT 1024
#define GRID 128
#define THREADS 256
#define ROWS_CTA 64
#define KC 64
#define A_PITCH 33   // float4 per row (64 k / 2), padded
#define Y_PITCH 36   // floats per row (32 cols), 16B-aligned pitch

__device__ volatile unsigned g_sense;
__device__ unsigned g_count;
__device__ float g_hbuf[2][NB * NH];

__device__ __forceinline__ unsigned long long pack2(float lo, float hi) {
    unsigned long long r;
    asm("mov.b64 %0, {%1,%2};" : "=l"(r) : "f"(lo), "f"(hi));
    return r;
}
__device__ __forceinline__ void unpack2(unsigned long long v, float& lo, float& hi) {
    asm("mov.b64 {%0,%1}, %2;" : "=f"(lo), "=f"(hi) : "l"(v));
}
#define FMA2(acc, a, w) \
    asm("fma.rn.f32x2 %0, %1, %2, %0;" : "+l"(acc) : "l"(a), "l"(w))

__device__ __forceinline__ float sigf(float x) { return 1.0f / (1.0f + expf(-x)); }

__global__ void __launch_bounds__(THREADS, 1) lstm_persistent(
    const float* __restrict__ obs, const float* __restrict__ Wi,
    const float* __restrict__ Wh, const float* __restrict__ bv,
    const float* __restrict__ c0, const float* __restrict__ h0,
    float* __restrict__ out, int out_size)
{
    extern __shared__ char smraw[];
    // W4: float4[1024][8]          131072 B  (cols 4j..4j+3 of this CTA's 32 gate cols)
    // A4: float4[64][A_PITCH]       33792 B  (a_k,a_k,a_{k+1},a_{k+1}) per entry
    // Yf: float [64][Y_PITCH]        9216 B  (gate pre-activations for combine)
    float4* W4 = (float4*)smraw;
    float4* A4 = (float4*)(smraw + 131072);
    float*  Yf = (float*)(smraw + 131072 + 33792);

    const int tid = threadIdx.x;
    const int tx3 = tid & 7;        // col-group: 4 gate cols 4*tx3..4*tx3+3
    const int tyr = tid >> 3;       // row-group: rows 2*tyr, 2*tyr+1
    const int r0 = 2 * tyr, r1 = 2 * tyr + 1;
    const int bi = blockIdx.x >> 6;
    const int hj = blockIdx.x & 63;
    const int row0 = bi * ROWS_CTA;
    const int hcol0 = hj * 8;

    // ---- one-time: fill W4 (rows 0..511 from Wi, 512..1023 from Wh) ----
    // local col c -> global gate col: ((c>>3)<<9) + hcol0 + (c&7); entry j covers 4 consecutive global cols
    for (int idx = tid; idx < K_TOT * 8; idx += THREADS) {
        int k = idx >> 3, j = idx & 7;
        int gbase = ((j >> 1) << 9) + hcol0 + ((j & 1) << 2);
        float4 v;
        if (k < ND) v = *(const float4*)&Wi[k * 2048 + gbase];
        else        v = *(const float4*)&Wh[(k - ND) * 2048 + gbase];
        W4[idx] = v;
    }

    // bias for this thread's 4 cols (2 f32x2 pairs)
    const int gcb = ((tx3 >> 1) << 9) + hcol0 + ((tx3 & 1) << 2);
    const unsigned long long bias_p0 = pack2(bv[gcb + 0], bv[gcb + 1]);
    const unsigned long long bias_p1 = pack2(bv[gcb + 2], bv[gcb + 3]);

    // elementwise ownership: two (row, hcol) pairs per thread; c kept in registers
    const int p0 = tid, p1 = tid + 256;
    const int r_p0 = p0 >> 3, h_p0 = p0 & 7;
    const int r_p1 = p1 >> 3, h_p1 = p1 & 7;
    const int gi0 = (row0 + r_p0) * NH + hcol0 + h_p0;
    const int gi1 = (row0 + r_p1) * NH + hcol0 + h_p1;
    float cs0 = c0[gi0], cs1 = c0[gi1];

    __syncthreads();

    const ulonglong2* a0p = (const ulonglong2*)(A4 + r0 * A_PITCH);
    const ulonglong2* a1p = (const ulonglong2*)(A4 + r1 * A_PITCH);
    float2 rg[8];

    for (int t = 0; t < NT; ++t) {
        const float* hsrc = (t == 0) ? h0 : (const float*)g_hbuf[t & 1];
        unsigned long long acc00 = bias_p0, acc01 = bias_p1;
        unsigned long long acc10 = bias_p0, acc11 = bias_p1;

        // prologue: load K-chunk 0 (pure obs) into registers (float2 = 2 k values)
        #pragma unroll
        for (int i = 0; i < 8; ++i) {
            int idx = tid + (i << 8);          // over 2048 float4 slots
            int r = idx >> 5, k2 = idx & 31;
            rg[i] = *(const float2*)&obs[((row0 + r) * NT + t) * ND + 2 * k2];
        }

        for (int ch = 0; ch < 16; ++ch) {
            __syncthreads();
            // store staged chunk to SMEM, duplicated pairs for f32x2 broadcast
            #pragma unroll
            for (int i = 0; i < 8; ++i) {
                int idx = tid + (i << 8);
                int r = idx >> 5, k2 = idx & 31;
                A4[r * A_PITCH + k2] = make_float4(rg[i].x, rg[i].x, rg[i].y, rg[i].y);
            }
            __syncthreads();
            // prefetch next chunk (chunks are homogeneous: ch<8 obs, ch>=8 h)
            if (ch < 15) {
                const int chn = ch + 1;
                if (chn < 8) {
                    const int kg0 = chn * KC;
                    #pragma unroll
                    for (int i = 0; i < 8; ++i) {
                        int idx = tid + (i << 8);
                        int r = idx >> 5, k2 = idx & 31;
                        rg[i] = *(const float2*)&obs[((row0 + r) * NT + t) * ND + kg0 + 2 * k2];
                    }
                } else {
                    const int kg0 = chn * KC - ND;
                    #pragma unroll
                    for (int i = 0; i < 8; ++i) {
                        int idx = tid + (i << 8);
                        int r = idx >> 5, k2 = idx & 31;
                        rg[i] = __ldcg((const float2*)(hsrc + (row0 + r) * NH + kg0 + 2 * k2));
                    }
                }
            }
            // compute: 32 k2-iters (64 k), 4 LDS.128 + 8 FMA2 each
            const ulonglong2* wp = (const ulonglong2*)(W4 + ch * KC * 8) + tx3;
            #pragma unroll 4
            for (int k2 = 0; k2 < 32; ++k2) {
                ulonglong2 w0 = wp[(2 * k2) * 8];
                ulonglong2 w1 = wp[(2 * k2 + 1) * 8];
                ulonglong2 a0 = a0p[k2];
                ulonglong2 a1 = a1p[k2];
                FMA2(acc00, a0.x, w0.x); FMA2(acc01, a0.x, w0.y);
                FMA2(acc10, a1.x, w0.x); FMA2(acc11, a1.x, w0.y);
                FMA2(acc00, a0.y, w1.x); FMA2(acc01, a0.y, w1.y);
                FMA2(acc10, a1.y, w1.x); FMA2(acc11, a1.y, w1.y);
            }
        }

        // publish gate pre-activations: one float4 per row = cols 4*tx3..4*tx3+3
        {
            float l0, h0v, l1, h1v;
            unpack2(acc00, l0, h0v); unpack2(acc01, l1, h1v);
            ((float4*)(Yf + r0 * Y_PITCH))[tx3] = make_float4(l0, h0v, l1, h1v);
            unpack2(acc10, l0, h0v); unpack2(acc11, l1, h1v);
            ((float4*)(Yf + r1 * Y_PITCH))[tx3] = make_float4(l0, h0v, l1, h1v);
        }
        __syncthreads();

        float hn0, hn1;
        {
            float iv = Yf[r_p0 * Y_PITCH + h_p0];
            float fv = Yf[r_p0 * Y_PITCH + 8 + h_p0];
            float gv = Yf[r_p0 * Y_PITCH + 16 + h_p0];
            float ov = Yf[r_p0 * Y_PITCH + 24 + h_p0];
            cs0 = sigf(fv) * cs0 + sigf(iv) * tanhf(gv);
            hn0 = sigf(ov) * tanhf(cs0);
        }
        {
            float iv = Yf[r_p1 * Y_PITCH + h_p1];
            float fv = Yf[r_p1 * Y_PITCH + 8 + h_p1];
            float gv = Yf[r_p1 * Y_PITCH + 16 + h_p1];
            float ov = Yf[r_p1 * Y_PITCH + 24 + h_p1];
            cs1 = sigf(fv) * cs1 + sigf(iv) * tanhf(gv);
            hn1 = sigf(ov) * tanhf(cs1);
        }

        // h for next step + contexts output
        float* hdst = g_hbuf[(t + 1) & 1];
        hdst[gi0] = hn0;
        hdst[gi1] = hn1;
        out[((row0 + r_p0) * NT + t) * NH + hcol0 + h_p0] = hn0;
        out[((row0 + r_p1) * NT + t) * NH + hcol0 + h_p1] = hn1;
        if (t == NT - 1) {
            int base = NB * NT * NH;
            if (out_size >= base + 2 * NB * NH) {
                out[base + gi0] = cs0;              // cT
                out[base + gi1] = cs1;
                out[base + NB * NH + gi0] = hn0;    // hT
                out[base + NB * NH + gi1] = hn1;
            }
        }

        // device-wide sense-reversal barrier
        __threadfence();
        __syncthreads();
        if (tid == 0) {
            const unsigned target = (unsigned)((t & 1) ^ 1);
            if (atomicAdd(&g_count, 1u) == GRID - 1) {
                g_count = 0;
                __threadfence();
                g_sense = target;
            } else {
                while (g_sense != target) { }
                __threadfence();
            }
        }
        __syncthreads();
    }
}

extern "C" void kernel_launch(void* const* d_in, const int* in_sizes, int n_in,
                              void* d_out, int out_size)
{
    const float* obs = (const float*)d_in[0];
    const float* Wi  = (const float*)d_in[1];
    const float* Wh  = (const float*)d_in[2];
    const float* bv  = (const float*)d_in[3];
    const float* c0  = (const float*)d_in[4];
    const float* h0  = (const float*)d_in[5];

    const int smem_bytes = 131072 + 33792 + 9216;  // 174,080 B
    cudaFuncSetAttribute(lstm_persistent,
                         cudaFuncAttributeMaxDynamicSharedMemorySize, smem_bytes);
    lstm_persistent<<<GRID, THREADS, smem_bytes>>>(obs, Wi, Wh, bv, c0, h0,
                                                   (float*)d_out, out_size);
}

// round 5
// speedup vs baseline: 1.0707x; 1.0015x over previous
#include <cuda_runtime.h>
#include <math.h>

// LSTM: B=128, T=1024, D=512, H=512.
// Persistent kernel: 128 CTAs = 2 batch tiles (64 rows) x 64 h-col tiles (8 h cols -> 32 gate cols).
// W slice resident in SMEM as float4 (4 packed gate cols); A duplicated-pair float4 covers 2 k per LDS.128.
// Per-thread tile: 2 rows x 2 f32x2 col-pairs -> 4 LDS.128 + 8 FMA2 per 2 k.

#define NB 128
#define NT 1024
#define ND 512
#define NH 512
#define K_TOT 1024
#define GRID 128
#define THREADS 256
#define ROWS_CTA 64
#define KC 64
#define A_PITCH 33   // float4 per row (64 k / 2), padded
#define Y_PITCH 36   // floats per row (32 cols), 16B-aligned pitch

__device__ volatile unsigned g_sense;
__device__ unsigned g_count;
__device__ float g_hbuf[2][NB * NH];

__device__ __forceinline__ unsigned long long pack2(float lo, float hi) {
    unsigned long long r;
    asm("mov.b64 %0, {%1,%2};" : "=l"(r) : "f"(lo), "f"(hi));
    return r;
}
__device__ __forceinline__ void unpack2(unsigned long long v, float& lo, float& hi) {
    asm("mov.b64 {%0,%1}, %2;" : "=f"(lo), "=f"(hi) : "l"(v));
}
#define FMA2(acc, a, w) \
    asm("fma.rn.f32x2 %0, %1, %2, %0;" : "+l"(acc) : "l"(a), "l"(w))

__device__ __forceinline__ float sigf(float x) { return 1.0f / (1.0f + expf(-x)); }

__global__ void __launch_bounds__(THREADS, 1) lstm_persistent(
    const float* __restrict__ obs, const float* __restrict__ Wi,
    const float* __restrict__ Wh, const float* __restrict__ bv,
    const float* __restrict__ c0, const float* __restrict__ h0,
    float* __restrict__ out, int out_size)
{
    extern __shared__ char smraw[];
    // W4: float4[1024][8]          131072 B  (cols 4j..4j+3 of this CTA's 32 gate cols)
    // A4: float4[64][A_PITCH]       33792 B  (a_k,a_k,a_{k+1},a_{k+1}) per entry
    // Yf: float [64][Y_PITCH]        9216 B  (gate pre-activations for combine)
    float4* W4 = (float4*)smraw;
    float4* A4 = (float4*)(smraw + 131072);
    float*  Yf = (float*)(smraw + 131072 + 33792);

    const int tid = threadIdx.x;
    const int tx3 = tid & 7;        // col-group: 4 gate cols 4*tx3..4*tx3+3
    const int tyr = tid >> 3;       // row-group: rows 2*tyr, 2*tyr+1
    const int r0 = 2 * tyr, r1 = 2 * tyr + 1;
    const int bi = blockIdx.x >> 6;
    const int hj = blockIdx.x & 63;
    const int row0 = bi * ROWS_CTA;
    const int hcol0 = hj * 8;

    // ---- one-time: fill W4 (rows 0..511 from Wi, 512..1023 from Wh) ----
    // local col c -> global gate col: ((c>>3)<<9) + hcol0 + (c&7); entry j covers 4 consecutive global cols
    for (int idx = tid; idx < K_TOT * 8; idx += THREADS) {
        int k = idx >> 3, j = idx & 7;
        int gbase = ((j >> 1) << 9) + hcol0 + ((j & 1) << 2);
        float4 v;
        if (k < ND) v = *(const float4*)&Wi[k * 2048 + gbase];
        else        v = *(const float4*)&Wh[(k - ND) * 2048 + gbase];
        W4[idx] = v;
    }

    // bias for this thread's 4 cols (2 f32x2 pairs)
    const int gcb = ((tx3 >> 1) << 9) + hcol0 + ((tx3 & 1) << 2);
    const unsigned long long bias_p0 = pack2(bv[gcb + 0], bv[gcb + 1]);
    const unsigned long long bias_p1 = pack2(bv[gcb + 2], bv[gcb + 3]);

    // elementwise ownership: two (row, hcol) pairs per thread; c kept in registers
    const int p0 = tid, p1 = tid + 256;
    const int r_p0 = p0 >> 3, h_p0 = p0 & 7;
    const int r_p1 = p1 >> 3, h_p1 = p1 & 7;
    const int gi0 = (row0 + r_p0) * NH + hcol0 + h_p0;
    const int gi1 = (row0 + r_p1) * NH + hcol0 + h_p1;
    float cs0 = c0[gi0], cs1 = c0[gi1];

    __syncthreads();

    const ulonglong2* a0p = (const ulonglong2*)(A4 + r0 * A_PITCH);
    const ulonglong2* a1p = (const ulonglong2*)(A4 + r1 * A_PITCH);
    float2 rg[8];

    for (int t = 0; t < NT; ++t) {
        const float* hsrc = (t == 0) ? h0 : (const float*)g_hbuf[t & 1];
        unsigned long long acc00 = bias_p0, acc01 = bias_p1;
        unsigned long long acc10 = bias_p0, acc11 = bias_p1;

        // prologue: load K-chunk 0 (pure obs) into registers (float2 = 2 k values)
        #pragma unroll
        for (int i = 0; i < 8; ++i) {
            int idx = tid + (i << 8);          // over 2048 float4 slots
            int r = idx >> 5, k2 = idx & 31;
            rg[i] = *(const float2*)&obs[((row0 + r) * NT + t) * ND + 2 * k2];
        }

        for (int ch = 0; ch < 16; ++ch) {
            __syncthreads();
            // store staged chunk to SMEM, duplicated pairs for f32x2 broadcast
            #pragma unroll
            for (int i = 0; i < 8; ++i) {
                int idx = tid + (i << 8);
                int r = idx >> 5, k2 = idx & 31;
                A4[r * A_PITCH + k2] = make_float4(rg[i].x, rg[i].x, rg[i].y, rg[i].y);
            }
            __syncthreads();
            // prefetch next chunk (chunks are homogeneous: ch<8 obs, ch>=8 h)
            if (ch < 15) {
                const int chn = ch + 1;
                if (chn < 8) {
                    const int kg0 = chn * KC;
                    #pragma unroll
                    for (int i = 0; i < 8; ++i) {
                        int idx = tid + (i << 8);
                        int r = idx >> 5, k2 = idx & 31;
                        rg[i] = *(const float2*)&obs[((row0 + r) * NT + t) * ND + kg0 + 2 * k2];
                    }
                } else {
                    const int kg0 = chn * KC - ND;
                    #pragma unroll
                    for (int i = 0; i < 8; ++i) {
                        int idx = tid + (i << 8);
                        int r = idx >> 5, k2 = idx & 31;
                        rg[i] = __ldcg((const float2*)(hsrc + (row0 + r) * NH + kg0 + 2 * k2));
                    }
                }
            }
            // compute: 32 k2-iters (64 k), 4 LDS.128 + 8 FMA2 each
            const ulonglong2* wp = (const ulonglong2*)(W4 + ch * KC * 8) + tx3;
            #pragma unroll 4
            for (int k2 = 0; k2 < 32; ++k2) {
                ulonglong2 w0 = wp[(2 * k2) * 8];
                ulonglong2 w1 = wp[(2 * k2 + 1) * 8];
                ulonglong2 a0 = a0p[k2];
                ulonglong2 a1 = a1p[k2];
                FMA2(acc00, a0.x, w0.x); FMA2(acc01, a0.x, w0.y);
                FMA2(acc10, a1.x, w0.x); FMA2(acc11, a1.x, w0.y);
                FMA2(acc00, a0.y, w1.x); FMA2(acc01, a0.y, w1.y);
                FMA2(acc10, a1.y, w1.x); FMA2(acc11, a1.y, w1.y);
            }
        }

        // publish gate pre-activations: one float4 per row = cols 4*tx3..4*tx3+3
        {
            float l0, h0v, l1, h1v;
            unpack2(acc00, l0, h0v); unpack2(acc01, l1, h1v);
            ((float4*)(Yf + r0 * Y_PITCH))[tx3] = make_float4(l0, h0v, l1, h1v);
            unpack2(acc10, l0, h0v); unpack2(acc11, l1, h1v);
            ((float4*)(Yf + r1 * Y_PITCH))[tx3] = make_float4(l0, h0v, l1, h1v);
        }
        __syncthreads();

        float hn0, hn1;
        {
            float iv = Yf[r_p0 * Y_PITCH + h_p0];
            float fv = Yf[r_p0 * Y_PITCH + 8 + h_p0];
            float gv = Yf[r_p0 * Y_PITCH + 16 + h_p0];
            float ov = Yf[r_p0 * Y_PITCH + 24 + h_p0];
            cs0 = sigf(fv) * cs0 + sigf(iv) * tanhf(gv);
            hn0 = sigf(ov) * tanhf(cs0);
        }
        {
            float iv = Yf[r_p1 * Y_PITCH + h_p1];
            float fv = Yf[r_p1 * Y_PITCH + 8 + h_p1];
            float gv = Yf[r_p1 * Y_PITCH + 16 + h_p1];
            float ov = Yf[r_p1 * Y_PITCH + 24 + h_p1];
            cs1 = sigf(fv) * cs1 + sigf(iv) * tanhf(gv);
            hn1 = sigf(ov) * tanhf(cs1);
        }

        // h for next step + contexts output
        float* hdst = g_hbuf[(t + 1) & 1];
        hdst[gi0] = hn0;
        hdst[gi1] = hn1;
        out[((row0 + r_p0) * NT + t) * NH + hcol0 + h_p0] = hn0;
        out[((row0 + r_p1) * NT + t) * NH + hcol0 + h_p1] = hn1;
        if (t == NT - 1) {
            int base = NB * NT * NH;
            if (out_size >= base + 2 * NB * NH) {
                out[base + gi0] = cs0;              // cT
                out[base + gi1] = cs1;
                out[base + NB * NH + gi0] = hn0;    // hT
                out[base + NB * NH + gi1] = hn1;
            }
        }

        // device-wide sense-reversal barrier
        __threadfence();
        __syncthreads();
        if (tid == 0) {
            const unsigned target = (unsigned)((t & 1) ^ 1);
            if (atomicAdd(&g_count, 1u) == GRID - 1) {
                g_count = 0;
                __threadfence();
                g_sense = target;
            } else {
                while (g_sense != target) { }
                __threadfence();
            }
        }
        __syncthreads();
    }
}

extern "C" void kernel_launch(void* const* d_in, const int* in_sizes, int n_in,
                              void* d_out, int out_size)
{
    const float* obs = (const float*)d_in[0];
    const float* Wi  = (const float*)d_in[1];
    const float* Wh  = (const float*)d_in[2];
    const float* bv  = (const float*)d_in[3];
    const float* c0  = (const float*)d_in[4];
    const float* h0  = (const float*)d_in[5];

    const int smem_bytes = 131072 + 33792 + 9216;  // 174,080 B
    cudaFuncSetAttribute(lstm_persistent,
                         cudaFuncAttributeMaxDynamicSharedMemorySize, smem_bytes);
    lstm_persistent<<<GRID, THREADS, smem_bytes>>>(obs, Wi, Wh, bv, c0, h0,
                                                   (float*)d_out, out_size);
}